// round 9
// baseline (speedup 1.0000x reference)
#include <cuda_runtime.h>

// ---------------- problem constants ----------------
#define NHEADS 4
#define KDIM   16
#define RESV   40
#define DIMC   256
#define HDC    64
#define DV     64
#define NPIX   1600
#define BATCH  16
#define EPSBN  1e-5f
#define SCALEF 0.25f

typedef unsigned long long ull;

// ---------------- scratch ----------------
__device__ float g_xi [BATCH*HDC*NPIX];
__device__ float g_q  [BATCH*KDIM*NPIX];
__device__ float g_k  [BATCH*KDIM*NPIX];
__device__ float g_vt [BATCH*NPIX*DV];      // [b][p][d]
__device__ float g_cat[BATCH*DIMC*NPIX];

// ---------------- f32x2 helpers ----------------
__device__ __forceinline__ ull f2pack(float x, float y){
    ull r; asm("mov.b64 %0, {%1, %2};" : "=l"(r) : "f"(x), "f"(y)); return r;
}
__device__ __forceinline__ float2 f2unpack(ull u){
    float2 r; asm("mov.b64 {%0, %1}, %2;" : "=f"(r.x), "=f"(r.y) : "l"(u)); return r;
}
__device__ __forceinline__ ull ffma2(ull a, ull b, ull c){
    ull r; asm("fma.rn.f32x2 %0, %1, %2, %3;" : "=l"(r) : "l"(a), "l"(b), "l"(c)); return r;
}
__device__ __forceinline__ ull fmul2(ull a, ull b){
    ull r; asm("mul.rn.f32x2 %0, %1, %2;" : "=l"(r) : "l"(a), "l"(b)); return r;
}
__device__ __forceinline__ ull fadd2(ull a, ull b){
    ull r; asm("add.rn.f32x2 %0, %1, %2;" : "=l"(r) : "l"(a), "l"(b)); return r;
}

// ================= 1) depthwise 5x5 conv + BN (+ cascade add) ================
__global__ __launch_bounds__(256) void dwconv_kernel(
    const float* __restrict__ x,
    const float* __restrict__ dw_w,
    const float* __restrict__ dw_g, const float* __restrict__ dw_b,
    const float* __restrict__ dw_m, const float* __restrict__ dw_v,
    int head)
{
    int idx = blockIdx.x * 256 + threadIdx.x;
    if (idx >= BATCH*HDC*NPIX) return;
    int p = idx % NPIX;
    int c = (idx / NPIX) % HDC;
    int b = idx / (NPIX*HDC);
    int h = p / RESV, w = p % RESV;
    int ci = head*HDC + c;

    const float* xs = x + ((size_t)b*DIMC + ci) * NPIX;
    const float* wf = dw_w + (size_t)ci * 25;

    float acc = 0.f;
    if (h >= 2 && h < RESV-2 && w >= 2 && w < RESV-2){
        const float* base = xs + (h-2)*RESV + (w-2);
        #pragma unroll
        for (int ky = 0; ky < 5; ky++)
            #pragma unroll
            for (int kx = 0; kx < 5; kx++)
                acc = fmaf(base[ky*RESV+kx], wf[ky*5+kx], acc);
    } else {
        #pragma unroll
        for (int ky = 0; ky < 5; ky++){
            int hy = h + ky - 2;
            if ((unsigned)hy >= (unsigned)RESV) continue;
            const float* row = xs + hy*RESV;
            #pragma unroll
            for (int kx = 0; kx < 5; kx++){
                int wx = w + kx - 2;
                if ((unsigned)wx < (unsigned)RESV)
                    acc = fmaf(row[wx], wf[ky*5+kx], acc);
            }
        }
    }
    float s   = dw_g[ci] * rsqrtf(dw_v[ci] + EPSBN);
    float val = (acc - dw_m[ci]) * s + dw_b[ci];
    if (head > 0)
        val += g_cat[((size_t)b*DIMC + (head-1)*DV + c)*NPIX + p];
    g_xi[idx] = val;
}

// ================= 2) QKV projections + BN (f32x2) ===========================
#define QKV_T 320
#define QKV_SMEM (64*320*4 + 48*64*8)

__global__ __launch_bounds__(QKV_T) void qkv_kernel(
    const float* __restrict__ q_w, const float* __restrict__ q_g,
    const float* __restrict__ q_b, const float* __restrict__ q_m,
    const float* __restrict__ q_v,
    const float* __restrict__ k_w, const float* __restrict__ k_g,
    const float* __restrict__ k_b, const float* __restrict__ k_m,
    const float* __restrict__ k_v,
    const float* __restrict__ v_w, const float* __restrict__ v_g,
    const float* __restrict__ v_b, const float* __restrict__ v_m,
    const float* __restrict__ v_v,
    int head)
{
    extern __shared__ float sm[];
    float* xt  = sm;                       // [64][320]
    ull*   wsm = (ull*)(sm + 64*320);      // [48][64] packed {w,w}

    const int tid = threadIdx.x;
    const int b   = blockIdx.y;
    const int z   = blockIdx.z;
    const int p0  = blockIdx.x * 320;

    const float* xb = g_xi + (size_t)b*HDC*NPIX + p0;
    for (int t = tid; t < 64*320; t += QKV_T){
        int c = t / 320, pp2 = t % 320;
        xt[t] = xb[(size_t)c*NPIX + pp2];
    }
    for (int t = tid; t < 48*64; t += QKV_T){
        int jl = t / 64, cc = t % 64;
        int jr = z*48 + jl;
        float wv;
        if (jr < 16)      wv = q_w[(size_t)(head*16 + jr)      *64 + cc];
        else if (jr < 32) wv = k_w[(size_t)(head*16 + jr - 16) *64 + cc];
        else              wv = v_w[(size_t)(head*64 + jr - 32) *64 + cc];
        wsm[t] = f2pack(wv, wv);
    }
    __syncthreads();

    const int pp   = tid % 160;
    const int jsub = tid / 160;
    const int px   = p0 + 2*pp;

    for (int jg = 0; jg < 3; jg++){
        const int jl = jsub*24 + jg*8;
        ull acc2[8];
        #pragma unroll
        for (int k = 0; k < 8; k++) acc2[k] = 0ull;

        for (int c = 0; c < 64; c++){
            ull xv2 = *(const ull*)&xt[c*320 + 2*pp];
            const ull* wr = &wsm[jl*64 + c];
            #pragma unroll
            for (int k = 0; k < 8; k++)
                acc2[k] = ffma2(wr[k*64], xv2, acc2[k]);
        }
        #pragma unroll
        for (int k = 0; k < 8; k++){
            float2 a = f2unpack(acc2[k]);
            int jr = z*48 + jl + k;
            if (jr < 16){
                int q = head*16 + jr;
                float sc = q_g[q]*rsqrtf(q_v[q]+EPSBN);
                float mu = q_m[q], be = q_b[q];
                g_q[((size_t)b*16 + jr)*NPIX + px]     = (a.x-mu)*sc + be;
                g_q[((size_t)b*16 + jr)*NPIX + px + 1] = (a.y-mu)*sc + be;
            } else if (jr < 32){
                int q = head*16 + jr - 16;
                float sc = k_g[q]*rsqrtf(k_v[q]+EPSBN);
                float mu = k_m[q], be = k_b[q];
                g_k[((size_t)b*16 + (jr-16))*NPIX + px]     = (a.x-mu)*sc + be;
                g_k[((size_t)b*16 + (jr-16))*NPIX + px + 1] = (a.y-mu)*sc + be;
            } else {
                int d = jr - 32;
                int q = head*64 + d;
                float sc = v_g[q]*rsqrtf(v_v[q]+EPSBN);
                float mu = v_m[q], be = v_b[q];
                g_vt[((size_t)b*NPIX + px)    *64 + d] = (a.x-mu)*sc + be;
                g_vt[((size_t)b*NPIX + px + 1)*64 + d] = (a.y-mu)*sc + be;
            }
        }
    }
}

// ================= 3) fused flash attention (warp-per-key-slice) =============
// 256 threads: warp w (0..7) owns keys [w*20, w*20+20); lane = query row.
// Each thread accumulates the FULL 64-dim output (f32x2 packed) for its row
// over its warp's keys; cross-warp reduce once at the end.
// smem floats: ks[16*160]=2560, vs[160*64]=10240, qs2(512 ull)=1024,
//              bsm[160], rr[8*32]=256  -> 14240 floats
#define ATTN_SMEM (14240*4)

__global__ __launch_bounds__(256, 2) void attn_kernel(
    const float* __restrict__ attn_bias, int head)
{
    extern __shared__ float sm[];
    float* ks  = sm;                       // [16][160]
    float* vs  = sm + 2560;                // [160][64]
    ull*   qs2 = (ull*)(sm + 12800);       // [16][32] packed {q,q}
    float* bsm = sm + 13824;               // [160]
    float* rr  = sm + 13984;               // [8][32]

    const int tid  = threadIdx.x;
    const int lane = tid & 31;
    const int w    = tid >> 5;
    const int b    = blockIdx.y;
    const int n0   = blockIdx.x * 32;
    const int k0   = w * 20;

    // q tile (scale folded), packed
    for (int t = tid; t < 512; t += 256){
        int kd = t >> 5, l = t & 31;
        float qv = g_q[((size_t)b*16 + kd)*NPIX + n0 + l] * SCALEF;
        qs2[t] = f2pack(qv, qv);
    }

    const float* kb  = g_k  + (size_t)b*16*NPIX;
    const float* vb  = g_vt + (size_t)b*NPIX*64;
    const float* bib = attn_bias + (size_t)head*NPIX;

    ull out2[32];
    #pragma unroll
    for (int i = 0; i < 32; i++) out2[i] = 0ull;
    float rowmax = -1e30f, rowsum = 0.f;

    for (int ch = 0; ch < 10; ch++){
        const int m0 = ch * 160;
        __syncthreads();
        for (int t = tid; t < 2560; t += 256){          // K [16][160]
            int kd = t / 160, mm = t - kd*160;
            ks[t] = kb[(size_t)kd*NPIX + m0 + mm];
        }
        for (int t = tid; t < 2560; t += 256){          // V [160][64]
            int m = t >> 4, d4 = t & 15;
            *(float4*)&vs[m*64 + d4*4] =
                *(const float4*)&vb[((size_t)(m0 + m))*64 + d4*4];
        }
        if (tid < 160) bsm[tid] = bib[m0 + tid];
        __syncthreads();

        // ---- logits for this warp's 20 keys (bias folded into init) ----
        ull acc[10];
        #pragma unroll
        for (int t = 0; t < 10; t++)
            acc[t] = *(const ull*)&bsm[k0 + 2*t];
        #pragma unroll
        for (int kd = 0; kd < 16; kd++){
            ull q2 = qs2[kd*32 + lane];
            const ull* kkp = (const ull*)&ks[kd*160 + k0];   // warp-uniform
            #pragma unroll
            for (int t = 0; t < 10; t++)
                acc[t] = ffma2(q2, kkp[t], acc[t]);
        }
        float pv[20];
        float lmax = -1e30f;
        #pragma unroll
        for (int t = 0; t < 10; t++){
            float2 l = f2unpack(acc[t]);
            pv[2*t] = l.x; pv[2*t+1] = l.y;
            lmax = fmaxf(lmax, fmaxf(l.x, l.y));
        }
        rr[w*32 + lane] = lmax;
        __syncthreads();

        float nm = rowmax;
        #pragma unroll
        for (int j = 0; j < 8; j++) nm = fmaxf(nm, rr[j*32 + lane]);
        float corr = __expf(rowmax - nm);
        rowmax = nm;
        rowsum *= corr;
        ull c2 = f2pack(corr, corr);
        #pragma unroll
        for (int i = 0; i < 32; i++) out2[i] = fmul2(out2[i], c2);

        float ls = 0.f;
        #pragma unroll
        for (int jj = 0; jj < 20; jj++){
            float p = __expf(pv[jj] - nm);
            pv[jj] = p;
            ls += p;
        }
        rowsum += ls;

        // ---- AV: warp-uniform V loads, p in registers ----
        #pragma unroll
        for (int jj = 0; jj < 20; jj++){
            ull p2 = f2pack(pv[jj], pv[jj]);
            const float* vrow = &vs[(k0 + jj)*64];
            #pragma unroll
            for (int d8 = 0; d8 < 8; d8++){
                ulonglong2 va = *(const ulonglong2*)&vrow[d8*8];
                ulonglong2 vc = *(const ulonglong2*)&vrow[d8*8 + 4];
                out2[d8*4 + 0] = ffma2(va.x, p2, out2[d8*4 + 0]);
                out2[d8*4 + 1] = ffma2(va.y, p2, out2[d8*4 + 1]);
                out2[d8*4 + 2] = ffma2(vc.x, p2, out2[d8*4 + 2]);
                out2[d8*4 + 3] = ffma2(vc.y, p2, out2[d8*4 + 3]);
            }
        }
    }

    // ---- row-sum across warps ----
    __syncthreads();
    rr[w*32 + lane] = rowsum;
    __syncthreads();
    float tot = 0.f;
    #pragma unroll
    for (int j = 0; j < 8; j++) tot += rr[j*32 + lane];
    float inv = 1.0f / tot;

    // ---- cross-warp output reduction (3-round tree into warp 0) ----
    float* buf = sm;                       // 4 slots of 32*68 (reuses ks/vs)
    // round 1: odd warps -> slot w>>1
    if (w & 1){
        float* dst = &buf[(w>>1)*2176 + lane*68];
        #pragma unroll
        for (int i = 0; i < 16; i++)
            *(ulonglong2*)&dst[i*4] = make_ulonglong2(out2[2*i], out2[2*i+1]);
    }
    __syncthreads();
    if (!(w & 1)){
        const float* src = &buf[(w>>1)*2176 + lane*68];
        #pragma unroll
        for (int i = 0; i < 16; i++){
            ulonglong2 vv = *(const ulonglong2*)&src[i*4];
            out2[2*i]   = fadd2(out2[2*i],   vv.x);
            out2[2*i+1] = fadd2(out2[2*i+1], vv.y);
        }
    }
    __syncthreads();
    // round 2: warps 2,6 -> slots 0,1
    if (w == 2 || w == 6){
        float* dst = &buf[(w>>2)*2176 + lane*68];
        #pragma unroll
        for (int i = 0; i < 16; i++)
            *(ulonglong2*)&dst[i*4] = make_ulonglong2(out2[2*i], out2[2*i+1]);
    }
    __syncthreads();
    if (w == 0 || w == 4){
        const float* src = &buf[(w>>2)*2176 + lane*68];
        #pragma unroll
        for (int i = 0; i < 16; i++){
            ulonglong2 vv = *(const ulonglong2*)&src[i*4];
            out2[2*i]   = fadd2(out2[2*i],   vv.x);
            out2[2*i+1] = fadd2(out2[2*i+1], vv.y);
        }
    }
    __syncthreads();
    // round 3: warp 4 -> slot 0
    if (w == 4){
        float* dst = &buf[lane*68];
        #pragma unroll
        for (int i = 0; i < 16; i++)
            *(ulonglong2*)&dst[i*4] = make_ulonglong2(out2[2*i], out2[2*i+1]);
    }
    __syncthreads();
    if (w == 0){
        const float* src = &buf[lane*68];
        ull i2 = f2pack(inv, inv);
        float* ob = g_cat + ((size_t)b*DIMC + head*64)*NPIX + n0 + lane;
        #pragma unroll
        for (int i = 0; i < 16; i++){
            ulonglong2 vv = *(const ulonglong2*)&src[i*4];
            ull o0 = fmul2(fadd2(out2[2*i],   vv.x), i2);
            ull o1 = fmul2(fadd2(out2[2*i+1], vv.y), i2);
            float2 f0 = f2unpack(o0), f1 = f2unpack(o1);
            ob[(size_t)(4*i + 0)*NPIX] = f0.x;
            ob[(size_t)(4*i + 1)*NPIX] = f0.y;
            ob[(size_t)(4*i + 2)*NPIX] = f1.x;
            ob[(size_t)(4*i + 3)*NPIX] = f1.y;
        }
    }
}

// ================= 4) final 256x256 projection + BN + ReLU (f32x2) ==========
#define PROJ_SMEM (64*65*8 + 64*64*4)

__global__ __launch_bounds__(256) void proj_kernel(
    const float* __restrict__ W,
    const float* __restrict__ pg, const float* __restrict__ pb,
    const float* __restrict__ pm, const float* __restrict__ pvv,
    float* __restrict__ out)
{
    extern __shared__ float smp[];
    ull*   Wt2 = (ull*)smp;                // [64][65] packed {w,w}
    float* Xt  = smp + 64*65*2;            // [64][64]

    const int tid = threadIdx.x;
    const int n0 = blockIdx.x * 64;
    const int o0 = blockIdx.y * 64;
    const int b  = blockIdx.z;
    const int tn = tid % 16, to = tid / 16;

    ull acc2[4][2];
    #pragma unroll
    for (int i = 0; i < 4; i++){ acc2[i][0] = 0ull; acc2[i][1] = 0ull; }

    for (int c0 = 0; c0 < 256; c0 += 64){
        __syncthreads();
        for (int t = tid; t < 4096; t += 256){
            int i = t / 64, j = t % 64;
            float wv = W[(size_t)(o0 + i)*256 + c0 + j];
            Wt2[i*65 + j] = f2pack(wv, wv);
            Xt[i*64 + j]  = g_cat[((size_t)b*DIMC + c0 + i)*NPIX + n0 + j];
        }
        __syncthreads();
        for (int c = 0; c < 64; c++){
            ull bx01 = *(const ull*)&Xt[c*64 + tn*4];
            ull bx23 = *(const ull*)&Xt[c*64 + tn*4 + 2];
            #pragma unroll
            for (int i = 0; i < 4; i++){
                ull a2 = Wt2[(to*4 + i)*65 + c];
                acc2[i][0] = ffma2(a2, bx01, acc2[i][0]);
                acc2[i][1] = ffma2(a2, bx23, acc2[i][1]);
            }
        }
    }
    #pragma unroll
    for (int i = 0; i < 4; i++){
        int o = o0 + to*4 + i;
        float s  = pg[o] * rsqrtf(pvv[o] + EPSBN);
        float mu = pm[o], be = pb[o];
        float2 a = f2unpack(acc2[i][0]);
        float2 c = f2unpack(acc2[i][1]);
        float4 v4;
        v4.x = fmaxf((a.x-mu)*s + be, 0.f);
        v4.y = fmaxf((a.y-mu)*s + be, 0.f);
        v4.z = fmaxf((c.x-mu)*s + be, 0.f);
        v4.w = fmaxf((c.y-mu)*s + be, 0.f);
        *(float4*)&out[((size_t)b*DIMC + o)*NPIX + n0 + tn*4] = v4;
    }
}

// ================= launch ====================================================
extern "C" void kernel_launch(void* const* d_in, const int* in_sizes, int n_in,
                              void* d_out, int out_size)
{
    const float* x      = (const float*)d_in[0];
    const float* dw_w   = (const float*)d_in[1];
    const float* dw_g   = (const float*)d_in[2];
    const float* dw_b   = (const float*)d_in[3];
    const float* dw_m   = (const float*)d_in[4];
    const float* dw_v   = (const float*)d_in[5];
    const float* q_w    = (const float*)d_in[6];
    const float* q_g    = (const float*)d_in[7];
    const float* q_b    = (const float*)d_in[8];
    const float* q_m    = (const float*)d_in[9];
    const float* q_v    = (const float*)d_in[10];
    const float* k_w    = (const float*)d_in[11];
    const float* k_g    = (const float*)d_in[12];
    const float* k_b    = (const float*)d_in[13];
    const float* k_m    = (const float*)d_in[14];
    const float* k_v    = (const float*)d_in[15];
    const float* v_w    = (const float*)d_in[16];
    const float* v_g    = (const float*)d_in[17];
    const float* v_b    = (const float*)d_in[18];
    const float* v_m    = (const float*)d_in[19];
    const float* v_v    = (const float*)d_in[20];
    const float* proj_w = (const float*)d_in[21];
    const float* proj_g = (const float*)d_in[22];
    const float* proj_b = (const float*)d_in[23];
    const float* proj_m = (const float*)d_in[24];
    const float* proj_v = (const float*)d_in[25];
    const float* attn_b = (const float*)d_in[26];

    cudaFuncSetAttribute(qkv_kernel,
        cudaFuncAttributeMaxDynamicSharedMemorySize, QKV_SMEM);
    cudaFuncSetAttribute(attn_kernel,
        cudaFuncAttributeMaxDynamicSharedMemorySize, ATTN_SMEM);
    cudaFuncSetAttribute(proj_kernel,
        cudaFuncAttributeMaxDynamicSharedMemorySize, PROJ_SMEM);

    const int dwTotal = BATCH*HDC*NPIX;
    for (int head = 0; head < NHEADS; head++){
        dwconv_kernel<<<(dwTotal + 255)/256, 256>>>(
            x, dw_w, dw_g, dw_b, dw_m, dw_v, head);
        qkv_kernel<<<dim3(5, BATCH, 2), QKV_T, QKV_SMEM>>>(
            q_w, q_g, q_b, q_m, q_v,
            k_w, k_g, k_b, k_m, k_v,
            v_w, v_g, v_b, v_m, v_v, head);
        attn_kernel<<<dim3(50, BATCH), 256, ATTN_SMEM>>>(attn_b, head);
    }
    proj_kernel<<<dim3(25, 4, BATCH), 256, PROJ_SMEM>>>(
        proj_w, proj_g, proj_b, proj_m, proj_v, (float*)d_out);
}

// round 10
// speedup vs baseline: 1.0011x; 1.0011x over previous
#include <cuda_runtime.h>

// ---------------- problem constants ----------------
#define NHEADS 4
#define KDIM   16
#define RESV   40
#define DIMC   256
#define HDC    64
#define DV     64
#define NPIX   1600
#define BATCH  16
#define EPSBN  1e-5f
#define SCALEF 0.25f

typedef unsigned long long ull;

// ---------------- scratch ----------------
__device__ float g_xi [BATCH*HDC*NPIX];
__device__ float g_q  [BATCH*KDIM*NPIX];
__device__ float g_k  [BATCH*KDIM*NPIX];
__device__ float g_vt [BATCH*NPIX*DV];      // [b][p][d]
__device__ float g_cat[BATCH*DIMC*NPIX];

// ---------------- f32x2 helpers ----------------
__device__ __forceinline__ ull f2pack(float x, float y){
    ull r; asm("mov.b64 %0, {%1, %2};" : "=l"(r) : "f"(x), "f"(y)); return r;
}
__device__ __forceinline__ float2 f2unpack(ull u){
    float2 r; asm("mov.b64 {%0, %1}, %2;" : "=f"(r.x), "=f"(r.y) : "l"(u)); return r;
}
__device__ __forceinline__ ull ffma2(ull a, ull b, ull c){
    ull r; asm("fma.rn.f32x2 %0, %1, %2, %3;" : "=l"(r) : "l"(a), "l"(b), "l"(c)); return r;
}
__device__ __forceinline__ ull fmul2(ull a, ull b){
    ull r; asm("mul.rn.f32x2 %0, %1, %2;" : "=l"(r) : "l"(a), "l"(b)); return r;
}
__device__ __forceinline__ ull fadd2(ull a, ull b){
    ull r; asm("add.rn.f32x2 %0, %1, %2;" : "=l"(r) : "l"(a), "l"(b)); return r;
}

// ================= 1) depthwise 5x5 conv + BN (+ cascade add) ================
__global__ __launch_bounds__(256) void dwconv_kernel(
    const float* __restrict__ x,
    const float* __restrict__ dw_w,
    const float* __restrict__ dw_g, const float* __restrict__ dw_b,
    const float* __restrict__ dw_m, const float* __restrict__ dw_v,
    int head)
{
    int idx = blockIdx.x * 256 + threadIdx.x;
    if (idx >= BATCH*HDC*NPIX) return;
    int p = idx % NPIX;
    int c = (idx / NPIX) % HDC;
    int b = idx / (NPIX*HDC);
    int h = p / RESV, w = p % RESV;
    int ci = head*HDC + c;

    const float* xs = x + ((size_t)b*DIMC + ci) * NPIX;
    const float* wf = dw_w + (size_t)ci * 25;

    float acc = 0.f;
    if (h >= 2 && h < RESV-2 && w >= 2 && w < RESV-2){
        const float* base = xs + (h-2)*RESV + (w-2);
        #pragma unroll
        for (int ky = 0; ky < 5; ky++)
            #pragma unroll
            for (int kx = 0; kx < 5; kx++)
                acc = fmaf(base[ky*RESV+kx], wf[ky*5+kx], acc);
    } else {
        #pragma unroll
        for (int ky = 0; ky < 5; ky++){
            int hy = h + ky - 2;
            if ((unsigned)hy >= (unsigned)RESV) continue;
            const float* row = xs + hy*RESV;
            #pragma unroll
            for (int kx = 0; kx < 5; kx++){
                int wx = w + kx - 2;
                if ((unsigned)wx < (unsigned)RESV)
                    acc = fmaf(row[wx], wf[ky*5+kx], acc);
            }
        }
    }
    float s   = dw_g[ci] * rsqrtf(dw_v[ci] + EPSBN);
    float val = (acc - dw_m[ci]) * s + dw_b[ci];
    if (head > 0)
        val += g_cat[((size_t)b*DIMC + (head-1)*DV + c)*NPIX + p];
    g_xi[idx] = val;
}

// ================= 2) QKV projections + BN (f32x2) ===========================
#define QKV_T 320
#define QKV_SMEM (64*320*4 + 48*64*8)

__global__ __launch_bounds__(QKV_T) void qkv_kernel(
    const float* __restrict__ q_w, const float* __restrict__ q_g,
    const float* __restrict__ q_b, const float* __restrict__ q_m,
    const float* __restrict__ q_v,
    const float* __restrict__ k_w, const float* __restrict__ k_g,
    const float* __restrict__ k_b, const float* __restrict__ k_m,
    const float* __restrict__ k_v,
    const float* __restrict__ v_w, const float* __restrict__ v_g,
    const float* __restrict__ v_b, const float* __restrict__ v_m,
    const float* __restrict__ v_v,
    int head)
{
    extern __shared__ float sm[];
    float* xt  = sm;                       // [64][320]
    ull*   wsm = (ull*)(sm + 64*320);      // [48][64] packed {w,w}

    const int tid = threadIdx.x;
    const int b   = blockIdx.y;
    const int z   = blockIdx.z;
    const int p0  = blockIdx.x * 320;

    const float* xb = g_xi + (size_t)b*HDC*NPIX + p0;
    for (int t = tid; t < 64*320; t += QKV_T){
        int c = t / 320, pp2 = t % 320;
        xt[t] = xb[(size_t)c*NPIX + pp2];
    }
    for (int t = tid; t < 48*64; t += QKV_T){
        int jl = t / 64, cc = t % 64;
        int jr = z*48 + jl;
        float wv;
        if (jr < 16)      wv = q_w[(size_t)(head*16 + jr)      *64 + cc];
        else if (jr < 32) wv = k_w[(size_t)(head*16 + jr - 16) *64 + cc];
        else              wv = v_w[(size_t)(head*64 + jr - 32) *64 + cc];
        wsm[t] = f2pack(wv, wv);
    }
    __syncthreads();

    const int pp   = tid % 160;
    const int jsub = tid / 160;
    const int px   = p0 + 2*pp;

    for (int jg = 0; jg < 3; jg++){
        const int jl = jsub*24 + jg*8;
        ull acc2[8];
        #pragma unroll
        for (int k = 0; k < 8; k++) acc2[k] = 0ull;

        for (int c = 0; c < 64; c++){
            ull xv2 = *(const ull*)&xt[c*320 + 2*pp];
            const ull* wr = &wsm[jl*64 + c];
            #pragma unroll
            for (int k = 0; k < 8; k++)
                acc2[k] = ffma2(wr[k*64], xv2, acc2[k]);
        }
        #pragma unroll
        for (int k = 0; k < 8; k++){
            float2 a = f2unpack(acc2[k]);
            int jr = z*48 + jl + k;
            if (jr < 16){
                int q = head*16 + jr;
                float sc = q_g[q]*rsqrtf(q_v[q]+EPSBN);
                float mu = q_m[q], be = q_b[q];
                g_q[((size_t)b*16 + jr)*NPIX + px]     = (a.x-mu)*sc + be;
                g_q[((size_t)b*16 + jr)*NPIX + px + 1] = (a.y-mu)*sc + be;
            } else if (jr < 32){
                int q = head*16 + jr - 16;
                float sc = k_g[q]*rsqrtf(k_v[q]+EPSBN);
                float mu = k_m[q], be = k_b[q];
                g_k[((size_t)b*16 + (jr-16))*NPIX + px]     = (a.x-mu)*sc + be;
                g_k[((size_t)b*16 + (jr-16))*NPIX + px + 1] = (a.y-mu)*sc + be;
            } else {
                int d = jr - 32;
                int q = head*64 + d;
                float sc = v_g[q]*rsqrtf(v_v[q]+EPSBN);
                float mu = v_m[q], be = v_b[q];
                g_vt[((size_t)b*NPIX + px)    *64 + d] = (a.x-mu)*sc + be;
                g_vt[((size_t)b*NPIX + px + 1)*64 + d] = (a.y-mu)*sc + be;
            }
        }
    }
}

// ================= 3) fused flash attention (warp-per-key-slice) =============
// 256 threads: warp w (0..7) owns keys [w*20, w*20+20); lane = query row.
// Each thread accumulates the FULL 64-dim output (f32x2 packed) for its row
// over its warp's keys; cross-warp reduce once at the end.
// smem floats: ks[16*160]=2560, vs[160*64]=10240, qs2(512 ull)=1024,
//              bsm[160], rr[8*32]=256  -> 14240 floats
#define ATTN_SMEM (14240*4)

__global__ __launch_bounds__(256, 2) void attn_kernel(
    const float* __restrict__ attn_bias, int head)
{
    extern __shared__ float sm[];
    float* ks  = sm;                       // [16][160]
    float* vs  = sm + 2560;                // [160][64]
    ull*   qs2 = (ull*)(sm + 12800);       // [16][32] packed {q,q}
    float* bsm = sm + 13824;               // [160]
    float* rr  = sm + 13984;               // [8][32]

    const int tid  = threadIdx.x;
    const int lane = tid & 31;
    const int w    = tid >> 5;
    const int b    = blockIdx.y;
    const int n0   = blockIdx.x * 32;
    const int k0   = w * 20;

    // q tile (scale folded), packed
    for (int t = tid; t < 512; t += 256){
        int kd = t >> 5, l = t & 31;
        float qv = g_q[((size_t)b*16 + kd)*NPIX + n0 + l] * SCALEF;
        qs2[t] = f2pack(qv, qv);
    }

    const float* kb  = g_k  + (size_t)b*16*NPIX;
    const float* vb  = g_vt + (size_t)b*NPIX*64;
    const float* bib = attn_bias + (size_t)head*NPIX;

    ull out2[32];
    #pragma unroll
    for (int i = 0; i < 32; i++) out2[i] = 0ull;
    float rowmax = -1e30f, rowsum = 0.f;

    for (int ch = 0; ch < 10; ch++){
        const int m0 = ch * 160;
        __syncthreads();
        for (int t = tid; t < 2560; t += 256){          // K [16][160]
            int kd = t / 160, mm = t - kd*160;
            ks[t] = kb[(size_t)kd*NPIX + m0 + mm];
        }
        for (int t = tid; t < 2560; t += 256){          // V [160][64]
            int m = t >> 4, d4 = t & 15;
            *(float4*)&vs[m*64 + d4*4] =
                *(const float4*)&vb[((size_t)(m0 + m))*64 + d4*4];
        }
        if (tid < 160) bsm[tid] = bib[m0 + tid];
        __syncthreads();

        // ---- logits for this warp's 20 keys (bias folded into init) ----
        ull acc[10];
        #pragma unroll
        for (int t = 0; t < 10; t++)
            acc[t] = *(const ull*)&bsm[k0 + 2*t];
        #pragma unroll
        for (int kd = 0; kd < 16; kd++){
            ull q2 = qs2[kd*32 + lane];
            const ull* kkp = (const ull*)&ks[kd*160 + k0];   // warp-uniform
            #pragma unroll
            for (int t = 0; t < 10; t++)
                acc[t] = ffma2(q2, kkp[t], acc[t]);
        }
        float pv[20];
        float lmax = -1e30f;
        #pragma unroll
        for (int t = 0; t < 10; t++){
            float2 l = f2unpack(acc[t]);
            pv[2*t] = l.x; pv[2*t+1] = l.y;
            lmax = fmaxf(lmax, fmaxf(l.x, l.y));
        }
        rr[w*32 + lane] = lmax;
        __syncthreads();

        float nm = rowmax;
        #pragma unroll
        for (int j = 0; j < 8; j++) nm = fmaxf(nm, rr[j*32 + lane]);
        float corr = __expf(rowmax - nm);
        rowmax = nm;
        rowsum *= corr;
        ull c2 = f2pack(corr, corr);
        #pragma unroll
        for (int i = 0; i < 32; i++) out2[i] = fmul2(out2[i], c2);

        float ls = 0.f;
        #pragma unroll
        for (int jj = 0; jj < 20; jj++){
            float p = __expf(pv[jj] - nm);
            pv[jj] = p;
            ls += p;
        }
        rowsum += ls;

        // ---- AV: warp-uniform V loads, p in registers ----
        #pragma unroll
        for (int jj = 0; jj < 20; jj++){
            ull p2 = f2pack(pv[jj], pv[jj]);
            const float* vrow = &vs[(k0 + jj)*64];
            #pragma unroll
            for (int d8 = 0; d8 < 8; d8++){
                ulonglong2 va = *(const ulonglong2*)&vrow[d8*8];
                ulonglong2 vc = *(const ulonglong2*)&vrow[d8*8 + 4];
                out2[d8*4 + 0] = ffma2(va.x, p2, out2[d8*4 + 0]);
                out2[d8*4 + 1] = ffma2(va.y, p2, out2[d8*4 + 1]);
                out2[d8*4 + 2] = ffma2(vc.x, p2, out2[d8*4 + 2]);
                out2[d8*4 + 3] = ffma2(vc.y, p2, out2[d8*4 + 3]);
            }
        }
    }

    // ---- row-sum across warps ----
    __syncthreads();
    rr[w*32 + lane] = rowsum;
    __syncthreads();
    float tot = 0.f;
    #pragma unroll
    for (int j = 0; j < 8; j++) tot += rr[j*32 + lane];
    float inv = 1.0f / tot;

    // ---- cross-warp output reduction (3-round tree into warp 0) ----
    float* buf = sm;                       // 4 slots of 32*68 (reuses ks/vs)
    // round 1: odd warps -> slot w>>1
    if (w & 1){
        float* dst = &buf[(w>>1)*2176 + lane*68];
        #pragma unroll
        for (int i = 0; i < 16; i++)
            *(ulonglong2*)&dst[i*4] = make_ulonglong2(out2[2*i], out2[2*i+1]);
    }
    __syncthreads();
    if (!(w & 1)){
        const float* src = &buf[(w>>1)*2176 + lane*68];
        #pragma unroll
        for (int i = 0; i < 16; i++){
            ulonglong2 vv = *(const ulonglong2*)&src[i*4];
            out2[2*i]   = fadd2(out2[2*i],   vv.x);
            out2[2*i+1] = fadd2(out2[2*i+1], vv.y);
        }
    }
    __syncthreads();
    // round 2: warps 2,6 -> slots 0,1
    if (w == 2 || w == 6){
        float* dst = &buf[(w>>2)*2176 + lane*68];
        #pragma unroll
        for (int i = 0; i < 16; i++)
            *(ulonglong2*)&dst[i*4] = make_ulonglong2(out2[2*i], out2[2*i+1]);
    }
    __syncthreads();
    if (w == 0 || w == 4){
        const float* src = &buf[(w>>2)*2176 + lane*68];
        #pragma unroll
        for (int i = 0; i < 16; i++){
            ulonglong2 vv = *(const ulonglong2*)&src[i*4];
            out2[2*i]   = fadd2(out2[2*i],   vv.x);
            out2[2*i+1] = fadd2(out2[2*i+1], vv.y);
        }
    }
    __syncthreads();
    // round 3: warp 4 -> slot 0
    if (w == 4){
        float* dst = &buf[lane*68];
        #pragma unroll
        for (int i = 0; i < 16; i++)
            *(ulonglong2*)&dst[i*4] = make_ulonglong2(out2[2*i], out2[2*i+1]);
    }
    __syncthreads();
    if (w == 0){
        const float* src = &buf[lane*68];
        ull i2 = f2pack(inv, inv);
        float* ob = g_cat + ((size_t)b*DIMC + head*64)*NPIX + n0 + lane;
        #pragma unroll
        for (int i = 0; i < 16; i++){
            ulonglong2 vv = *(const ulonglong2*)&src[i*4];
            ull o0 = fmul2(fadd2(out2[2*i],   vv.x), i2);
            ull o1 = fmul2(fadd2(out2[2*i+1], vv.y), i2);
            float2 f0 = f2unpack(o0), f1 = f2unpack(o1);
            ob[(size_t)(4*i + 0)*NPIX] = f0.x;
            ob[(size_t)(4*i + 1)*NPIX] = f0.y;
            ob[(size_t)(4*i + 2)*NPIX] = f1.x;
            ob[(size_t)(4*i + 3)*NPIX] = f1.y;
        }
    }
}

// ================= 4) final 256x256 projection + BN + ReLU (f32x2) ==========
#define PROJ_SMEM (64*65*8 + 64*64*4)

__global__ __launch_bounds__(256) void proj_kernel(
    const float* __restrict__ W,
    const float* __restrict__ pg, const float* __restrict__ pb,
    const float* __restrict__ pm, const float* __restrict__ pvv,
    float* __restrict__ out)
{
    extern __shared__ float smp[];
    ull*   Wt2 = (ull*)smp;                // [64][65] packed {w,w}
    float* Xt  = smp + 64*65*2;            // [64][64]

    const int tid = threadIdx.x;
    const int n0 = blockIdx.x * 64;
    const int o0 = blockIdx.y * 64;
    const int b  = blockIdx.z;
    const int tn = tid % 16, to = tid / 16;

    ull acc2[4][2];
    #pragma unroll
    for (int i = 0; i < 4; i++){ acc2[i][0] = 0ull; acc2[i][1] = 0ull; }

    for (int c0 = 0; c0 < 256; c0 += 64){
        __syncthreads();
        for (int t = tid; t < 4096; t += 256){
            int i = t / 64, j = t % 64;
            float wv = W[(size_t)(o0 + i)*256 + c0 + j];
            Wt2[i*65 + j] = f2pack(wv, wv);
            Xt[i*64 + j]  = g_cat[((size_t)b*DIMC + c0 + i)*NPIX + n0 + j];
        }
        __syncthreads();
        for (int c = 0; c < 64; c++){
            ull bx01 = *(const ull*)&Xt[c*64 + tn*4];
            ull bx23 = *(const ull*)&Xt[c*64 + tn*4 + 2];
            #pragma unroll
            for (int i = 0; i < 4; i++){
                ull a2 = Wt2[(to*4 + i)*65 + c];
                acc2[i][0] = ffma2(a2, bx01, acc2[i][0]);
                acc2[i][1] = ffma2(a2, bx23, acc2[i][1]);
            }
        }
    }
    #pragma unroll
    for (int i = 0; i < 4; i++){
        int o = o0 + to*4 + i;
        float s  = pg[o] * rsqrtf(pvv[o] + EPSBN);
        float mu = pm[o], be = pb[o];
        float2 a = f2unpack(acc2[i][0]);
        float2 c = f2unpack(acc2[i][1]);
        float4 v4;
        v4.x = fmaxf((a.x-mu)*s + be, 0.f);
        v4.y = fmaxf((a.y-mu)*s + be, 0.f);
        v4.z = fmaxf((c.x-mu)*s + be, 0.f);
        v4.w = fmaxf((c.y-mu)*s + be, 0.f);
        *(float4*)&out[((size_t)b*DIMC + o)*NPIX + n0 + tn*4] = v4;
    }
}

// ================= launch ====================================================
extern "C" void kernel_launch(void* const* d_in, const int* in_sizes, int n_in,
                              void* d_out, int out_size)
{
    const float* x      = (const float*)d_in[0];
    const float* dw_w   = (const float*)d_in[1];
    const float* dw_g   = (const float*)d_in[2];
    const float* dw_b   = (const float*)d_in[3];
    const float* dw_m   = (const float*)d_in[4];
    const float* dw_v   = (const float*)d_in[5];
    const float* q_w    = (const float*)d_in[6];
    const float* q_g    = (const float*)d_in[7];
    const float* q_b    = (const float*)d_in[8];
    const float* q_m    = (const float*)d_in[9];
    const float* q_v    = (const float*)d_in[10];
    const float* k_w    = (const float*)d_in[11];
    const float* k_g    = (const float*)d_in[12];
    const float* k_b    = (const float*)d_in[13];
    const float* k_m    = (const float*)d_in[14];
    const float* k_v    = (const float*)d_in[15];
    const float* v_w    = (const float*)d_in[16];
    const float* v_g    = (const float*)d_in[17];
    const float* v_b    = (const float*)d_in[18];
    const float* v_m    = (const float*)d_in[19];
    const float* v_v    = (const float*)d_in[20];
    const float* proj_w = (const float*)d_in[21];
    const float* proj_g = (const float*)d_in[22];
    const float* proj_b = (const float*)d_in[23];
    const float* proj_m = (const float*)d_in[24];
    const float* proj_v = (const float*)d_in[25];
    const float* attn_b = (const float*)d_in[26];

    cudaFuncSetAttribute(qkv_kernel,
        cudaFuncAttributeMaxDynamicSharedMemorySize, QKV_SMEM);
    cudaFuncSetAttribute(attn_kernel,
        cudaFuncAttributeMaxDynamicSharedMemorySize, ATTN_SMEM);
    cudaFuncSetAttribute(proj_kernel,
        cudaFuncAttributeMaxDynamicSharedMemorySize, PROJ_SMEM);

    const int dwTotal = BATCH*HDC*NPIX;
    for (int head = 0; head < NHEADS; head++){
        dwconv_kernel<<<(dwTotal + 255)/256, 256>>>(
            x, dw_w, dw_g, dw_b, dw_m, dw_v, head);
        qkv_kernel<<<dim3(5, BATCH, 2), QKV_T, QKV_SMEM>>>(
            q_w, q_g, q_b, q_m, q_v,
            k_w, k_g, k_b, k_m, k_v,
            v_w, v_g, v_b, v_m, v_v, head);
        attn_kernel<<<dim3(50, BATCH), 256, ATTN_SMEM>>>(attn_b, head);
    }
    proj_kernel<<<dim3(25, 4, BATCH), 256, PROJ_SMEM>>>(
        proj_w, proj_g, proj_b, proj_m, proj_v, (float*)d_out);
}

// round 11
// speedup vs baseline: 1.0813x; 1.0801x over previous
#include <cuda_runtime.h>

// ---------------- problem constants ----------------
#define NHEADS 4
#define KDIM   16
#define RESV   40
#define DIMC   256
#define HDC    64
#define DV     64
#define NPIX   1600
#define BATCH  16
#define EPSBN  1e-5f
#define SCALEF 0.25f

typedef unsigned long long ull;

// ---------------- scratch ----------------
__device__ float g_xi [BATCH*HDC*NPIX];
__device__ float g_q  [BATCH*KDIM*NPIX];
__device__ float g_k  [BATCH*KDIM*NPIX];
__device__ float g_vt [BATCH*NPIX*DV];      // [b][p][d]
__device__ float g_cat[BATCH*DIMC*NPIX];

// ---------------- f32x2 helpers ----------------
__device__ __forceinline__ ull f2pack(float x, float y){
    ull r; asm("mov.b64 %0, {%1, %2};" : "=l"(r) : "f"(x), "f"(y)); return r;
}
__device__ __forceinline__ float2 f2unpack(ull u){
    float2 r; asm("mov.b64 {%0, %1}, %2;" : "=f"(r.x), "=f"(r.y) : "l"(u)); return r;
}
__device__ __forceinline__ ull ffma2(ull a, ull b, ull c){
    ull r; asm("fma.rn.f32x2 %0, %1, %2, %3;" : "=l"(r) : "l"(a), "l"(b), "l"(c)); return r;
}
__device__ __forceinline__ ull fmul2(ull a, ull b){
    ull r; asm("mul.rn.f32x2 %0, %1, %2;" : "=l"(r) : "l"(a), "l"(b)); return r;
}
__device__ __forceinline__ ull fadd2(ull a, ull b){
    ull r; asm("add.rn.f32x2 %0, %1, %2;" : "=l"(r) : "l"(a), "l"(b)); return r;
}

// ---------------- cp.async helpers ----------------
__device__ __forceinline__ void cp16(void* dst, const void* src){
    unsigned s = (unsigned)__cvta_generic_to_shared(dst);
    asm volatile("cp.async.cg.shared.global [%0], [%1], 16;" :: "r"(s), "l"(src));
}
#define CP_COMMIT() asm volatile("cp.async.commit_group;" ::: "memory")
#define CP_WAIT0()  asm volatile("cp.async.wait_group 0;"  ::: "memory")

// ================= 1) depthwise 5x5 conv + BN (+ cascade add) ================
// One block per (b, c): zero-padded 44x44 smem tile -> no boundary branches,
// no per-pixel index div/mod for loads, weights broadcast from smem.
__global__ __launch_bounds__(256) void dwconv_kernel(
    const float* __restrict__ x,
    const float* __restrict__ dw_w,
    const float* __restrict__ dw_g, const float* __restrict__ dw_b,
    const float* __restrict__ dw_m, const float* __restrict__ dw_v,
    int head)
{
    __shared__ float tile[44*44];
    __shared__ float wsh[25];

    const int tid = threadIdx.x;
    const int c   = blockIdx.x & 63;
    const int b   = blockIdx.x >> 6;
    const int ci  = head*HDC + c;

    const float* xs = x + ((size_t)b*DIMC + ci) * NPIX;

    for (int t = tid; t < 44*44; t += 256) tile[t] = 0.f;
    if (tid < 25) wsh[tid] = dw_w[(size_t)ci*25 + tid];
    __syncthreads();
    for (int t = tid; t < NPIX; t += 256){
        int h = t / 40, w = t - h*40;
        tile[(h+2)*44 + (w+2)] = xs[t];
    }
    __syncthreads();

    const float s  = dw_g[ci] * rsqrtf(dw_v[ci] + EPSBN);
    const float mu = dw_m[ci], be = dw_b[ci];
    const float* prev = g_cat + ((size_t)b*DIMC + (head-1)*DV + c)*NPIX;
    float* xo = g_xi + ((size_t)b*HDC + c)*NPIX;

    for (int t = tid; t < NPIX; t += 256){
        int h = t / 40, w = t - h*40;
        const float* base = &tile[h*44 + w];
        float acc = 0.f;
        #pragma unroll
        for (int ky = 0; ky < 5; ky++)
            #pragma unroll
            for (int kx = 0; kx < 5; kx++)
                acc = fmaf(base[ky*44 + kx], wsh[ky*5 + kx], acc);
        float val = (acc - mu)*s + be;
        if (head > 0) val += prev[t];
        xo[t] = val;
    }
}

// ================= 2) QKV projections + BN (f32x2) ===========================
#define QKV_T 320
#define QKV_SMEM (64*320*4 + 48*64*8)

__global__ __launch_bounds__(QKV_T) void qkv_kernel(
    const float* __restrict__ q_w, const float* __restrict__ q_g,
    const float* __restrict__ q_b, const float* __restrict__ q_m,
    const float* __restrict__ q_v,
    const float* __restrict__ k_w, const float* __restrict__ k_g,
    const float* __restrict__ k_b, const float* __restrict__ k_m,
    const float* __restrict__ k_v,
    const float* __restrict__ v_w, const float* __restrict__ v_g,
    const float* __restrict__ v_b, const float* __restrict__ v_m,
    const float* __restrict__ v_v,
    int head)
{
    extern __shared__ float sm[];
    float* xt  = sm;                       // [64][320]
    ull*   wsm = (ull*)(sm + 64*320);      // [48][64] packed {w,w}

    const int tid = threadIdx.x;
    const int b   = blockIdx.y;
    const int z   = blockIdx.z;
    const int p0  = blockIdx.x * 320;

    const float* xb = g_xi + (size_t)b*HDC*NPIX + p0;
    for (int t = tid; t < 64*320; t += QKV_T){
        int c = t / 320, pp2 = t % 320;
        xt[t] = xb[(size_t)c*NPIX + pp2];
    }
    for (int t = tid; t < 48*64; t += QKV_T){
        int jl = t / 64, cc = t % 64;
        int jr = z*48 + jl;
        float wv;
        if (jr < 16)      wv = q_w[(size_t)(head*16 + jr)      *64 + cc];
        else if (jr < 32) wv = k_w[(size_t)(head*16 + jr - 16) *64 + cc];
        else              wv = v_w[(size_t)(head*64 + jr - 32) *64 + cc];
        wsm[t] = f2pack(wv, wv);
    }
    __syncthreads();

    const int pp   = tid % 160;
    const int jsub = tid / 160;
    const int px   = p0 + 2*pp;

    for (int jg = 0; jg < 3; jg++){
        const int jl = jsub*24 + jg*8;
        ull acc2[8];
        #pragma unroll
        for (int k = 0; k < 8; k++) acc2[k] = 0ull;

        for (int c = 0; c < 64; c++){
            ull xv2 = *(const ull*)&xt[c*320 + 2*pp];
            const ull* wr = &wsm[jl*64 + c];
            #pragma unroll
            for (int k = 0; k < 8; k++)
                acc2[k] = ffma2(wr[k*64], xv2, acc2[k]);
        }
        #pragma unroll
        for (int k = 0; k < 8; k++){
            float2 a = f2unpack(acc2[k]);
            int jr = z*48 + jl + k;
            if (jr < 16){
                int q = head*16 + jr;
                float sc = q_g[q]*rsqrtf(q_v[q]+EPSBN);
                float mu = q_m[q], be = q_b[q];
                g_q[((size_t)b*16 + jr)*NPIX + px]     = (a.x-mu)*sc + be;
                g_q[((size_t)b*16 + jr)*NPIX + px + 1] = (a.y-mu)*sc + be;
            } else if (jr < 32){
                int q = head*16 + jr - 16;
                float sc = k_g[q]*rsqrtf(k_v[q]+EPSBN);
                float mu = k_m[q], be = k_b[q];
                g_k[((size_t)b*16 + (jr-16))*NPIX + px]     = (a.x-mu)*sc + be;
                g_k[((size_t)b*16 + (jr-16))*NPIX + px + 1] = (a.y-mu)*sc + be;
            } else {
                int d = jr - 32;
                int q = head*64 + d;
                float sc = v_g[q]*rsqrtf(v_v[q]+EPSBN);
                float mu = v_m[q], be = v_b[q];
                g_vt[((size_t)b*NPIX + px)    *64 + d] = (a.x-mu)*sc + be;
                g_vt[((size_t)b*NPIX + px + 1)*64 + d] = (a.y-mu)*sc + be;
            }
        }
    }
}

// ================= 3) fused flash attention ==================================
// 256 threads, occ=1 (full register budget, no spills). Warp w owns keys
// [w*20, w*20+20); lane = query row. Double-buffered K/V/bias via cp.async.
// smem floats: ks[2][2560], vs[2][10240], bsm[2][160], qs2(512 ull), rr[8][32]
#define ATTN_SMEM (27200*4)

__global__ __launch_bounds__(256, 1) void attn_kernel(
    const float* __restrict__ attn_bias, int head)
{
    extern __shared__ float sm[];
    float* ks  = sm;                       // [2][16][160]
    float* vs  = sm + 5120;                // [2][160][64]
    float* bsm = sm + 25600;               // [2][160]
    ull*   qs2 = (ull*)(sm + 25920);       // [16][32] packed {q,q}
    float* rr  = sm + 26944;               // [8][32]

    const int tid  = threadIdx.x;
    const int lane = tid & 31;
    const int w    = tid >> 5;
    const int b    = blockIdx.y;
    const int n0   = blockIdx.x * 32;
    const int k0   = w * 20;

    const float* kb  = g_k  + (size_t)b*16*NPIX;
    const float* vb  = g_vt + (size_t)b*NPIX*64;
    const float* bib = attn_bias + (size_t)head*NPIX;

    // q tile (scale folded), packed
    for (int t = tid; t < 512; t += 256){
        int kd = t >> 5, l = t & 31;
        float qv = g_q[((size_t)b*16 + kd)*NPIX + n0 + l] * SCALEF;
        qs2[t] = f2pack(qv, qv);
    }

    // ---- prologue: async-load chunk 0 ----
    {
        float* ksb = ks;  float* vsb = vs;  float* bsb = bsm;
        for (int t = tid; t < 640; t += 256){
            int kd = t / 40, mm = (t % 40) * 4;
            cp16(&ksb[kd*160 + mm], &kb[(size_t)kd*NPIX + mm]);
        }
        for (int t = tid; t < 2560; t += 256){
            int m = t >> 4, d = (t & 15) * 4;
            cp16(&vsb[m*64 + d], &vb[(size_t)m*64 + d]);
        }
        if (tid < 40) cp16(&bsb[tid*4], &bib[tid*4]);
        CP_COMMIT();
    }
    CP_WAIT0();
    __syncthreads();

    ull out2[32];
    #pragma unroll
    for (int i = 0; i < 32; i++) out2[i] = 0ull;
    float rowmax = -1e30f, rowsum = 0.f;

    for (int ch = 0; ch < 10; ch++){
        const int cur = ch & 1;
        float* ksb = ks  + cur*2560;
        float* vsb = vs  + cur*10240;
        float* bsb = bsm + cur*160;

        // ---- prefetch chunk ch+1 into the other buffer ----
        if (ch < 9){
            const int m1 = (ch+1)*160;
            float* ksn = ks  + (1-cur)*2560;
            float* vsn = vs  + (1-cur)*10240;
            float* bsn = bsm + (1-cur)*160;
            for (int t = tid; t < 640; t += 256){
                int kd = t / 40, mm = (t % 40) * 4;
                cp16(&ksn[kd*160 + mm], &kb[(size_t)kd*NPIX + m1 + mm]);
            }
            for (int t = tid; t < 2560; t += 256){
                int m = t >> 4, d = (t & 15) * 4;
                cp16(&vsn[m*64 + d], &vb[(size_t)(m1 + m)*64 + d]);
            }
            if (tid < 40) cp16(&bsn[tid*4], &bib[m1 + tid*4]);
            CP_COMMIT();
        }

        // ---- logits for this warp's 20 keys (bias folded into init) ----
        ull acc[10];
        #pragma unroll
        for (int t = 0; t < 10; t++)
            acc[t] = *(const ull*)&bsb[k0 + 2*t];
        #pragma unroll
        for (int kd = 0; kd < 16; kd++){
            ull q2 = qs2[kd*32 + lane];
            const ull* kkp = (const ull*)&ksb[kd*160 + k0];   // warp-uniform
            #pragma unroll
            for (int t = 0; t < 10; t++)
                acc[t] = ffma2(q2, kkp[t], acc[t]);
        }
        float pv[20];
        float lmax = -1e30f;
        #pragma unroll
        for (int t = 0; t < 10; t++){
            float2 l = f2unpack(acc[t]);
            pv[2*t] = l.x; pv[2*t+1] = l.y;
            lmax = fmaxf(lmax, fmaxf(l.x, l.y));
        }
        rr[w*32 + lane] = lmax;
        __syncthreads();

        float nm = rowmax;
        #pragma unroll
        for (int j = 0; j < 8; j++) nm = fmaxf(nm, rr[j*32 + lane]);
        float corr = __expf(rowmax - nm);
        rowmax = nm;
        rowsum *= corr;
        ull c2 = f2pack(corr, corr);
        #pragma unroll
        for (int i = 0; i < 32; i++) out2[i] = fmul2(out2[i], c2);

        float ls = 0.f;
        #pragma unroll
        for (int jj = 0; jj < 20; jj++){
            float p = __expf(pv[jj] - nm);
            pv[jj] = p;
            ls += p;
        }
        rowsum += ls;

        // ---- AV: warp-uniform V loads, p in registers ----
        #pragma unroll
        for (int jj = 0; jj < 20; jj++){
            ull p2 = f2pack(pv[jj], pv[jj]);
            const float* vrow = &vsb[(k0 + jj)*64];
            #pragma unroll
            for (int d8 = 0; d8 < 8; d8++){
                ulonglong2 va = *(const ulonglong2*)&vrow[d8*8];
                ulonglong2 vc = *(const ulonglong2*)&vrow[d8*8 + 4];
                out2[d8*4 + 0] = ffma2(va.x, p2, out2[d8*4 + 0]);
                out2[d8*4 + 1] = ffma2(va.y, p2, out2[d8*4 + 1]);
                out2[d8*4 + 2] = ffma2(vc.x, p2, out2[d8*4 + 2]);
                out2[d8*4 + 3] = ffma2(vc.y, p2, out2[d8*4 + 3]);
            }
        }

        // prefetch must land + everyone done with buffers before swap
        CP_WAIT0();
        __syncthreads();
    }

    // ---- row-sum across warps ----
    rr[w*32 + lane] = rowsum;
    __syncthreads();
    float tot = 0.f;
    #pragma unroll
    for (int j = 0; j < 8; j++) tot += rr[j*32 + lane];
    float inv = 1.0f / tot;

    // ---- cross-warp output reduction (3-round tree into warp 0) ----
    float* buf = sm;                       // 4 slots of 32*68 floats
    if (w & 1){
        float* dst = &buf[(w>>1)*2176 + lane*68];
        #pragma unroll
        for (int i = 0; i < 16; i++)
            *(ulonglong2*)&dst[i*4] = make_ulonglong2(out2[2*i], out2[2*i+1]);
    }
    __syncthreads();
    if (!(w & 1)){
        const float* src = &buf[(w>>1)*2176 + lane*68];
        #pragma unroll
        for (int i = 0; i < 16; i++){
            ulonglong2 vv = *(const ulonglong2*)&src[i*4];
            out2[2*i]   = fadd2(out2[2*i],   vv.x);
            out2[2*i+1] = fadd2(out2[2*i+1], vv.y);
        }
    }
    __syncthreads();
    if (w == 2 || w == 6){
        float* dst = &buf[(w>>2)*2176 + lane*68];
        #pragma unroll
        for (int i = 0; i < 16; i++)
            *(ulonglong2*)&dst[i*4] = make_ulonglong2(out2[2*i], out2[2*i+1]);
    }
    __syncthreads();
    if (w == 0 || w == 4){
        const float* src = &buf[(w>>2)*2176 + lane*68];
        #pragma unroll
        for (int i = 0; i < 16; i++){
            ulonglong2 vv = *(const ulonglong2*)&src[i*4];
            out2[2*i]   = fadd2(out2[2*i],   vv.x);
            out2[2*i+1] = fadd2(out2[2*i+1], vv.y);
        }
    }
    __syncthreads();
    if (w == 4){
        float* dst = &buf[lane*68];
        #pragma unroll
        for (int i = 0; i < 16; i++)
            *(ulonglong2*)&dst[i*4] = make_ulonglong2(out2[2*i], out2[2*i+1]);
    }
    __syncthreads();
    if (w == 0){
        const float* src = &buf[lane*68];
        ull i2 = f2pack(inv, inv);
        float* ob = g_cat + ((size_t)b*DIMC + head*64)*NPIX + n0 + lane;
        #pragma unroll
        for (int i = 0; i < 16; i++){
            ulonglong2 vv = *(const ulonglong2*)&src[i*4];
            ull o0 = fmul2(fadd2(out2[2*i],   vv.x), i2);
            ull o1 = fmul2(fadd2(out2[2*i+1], vv.y), i2);
            float2 f0 = f2unpack(o0), f1 = f2unpack(o1);
            ob[(size_t)(4*i + 0)*NPIX] = f0.x;
            ob[(size_t)(4*i + 1)*NPIX] = f0.y;
            ob[(size_t)(4*i + 2)*NPIX] = f1.x;
            ob[(size_t)(4*i + 3)*NPIX] = f1.y;
        }
    }
}

// ================= 4) final 256x256 projection + BN + ReLU (f32x2) ==========
#define PROJ_SMEM (64*65*8 + 64*64*4)

__global__ __launch_bounds__(256) void proj_kernel(
    const float* __restrict__ W,
    const float* __restrict__ pg, const float* __restrict__ pb,
    const float* __restrict__ pm, const float* __restrict__ pvv,
    float* __restrict__ out)
{
    extern __shared__ float smp[];
    ull*   Wt2 = (ull*)smp;                // [64][65] packed {w,w}
    float* Xt  = smp + 64*65*2;            // [64][64]

    const int tid = threadIdx.x;
    const int n0 = blockIdx.x * 64;
    const int o0 = blockIdx.y * 64;
    const int b  = blockIdx.z;
    const int tn = tid % 16, to = tid / 16;

    ull acc2[4][2];
    #pragma unroll
    for (int i = 0; i < 4; i++){ acc2[i][0] = 0ull; acc2[i][1] = 0ull; }

    for (int c0 = 0; c0 < 256; c0 += 64){
        __syncthreads();
        for (int t = tid; t < 4096; t += 256){
            int i = t / 64, j = t % 64;
            float wv = W[(size_t)(o0 + i)*256 + c0 + j];
            Wt2[i*65 + j] = f2pack(wv, wv);
            Xt[i*64 + j]  = g_cat[((size_t)b*DIMC + c0 + i)*NPIX + n0 + j];
        }
        __syncthreads();
        for (int c = 0; c < 64; c++){
            ull bx01 = *(const ull*)&Xt[c*64 + tn*4];
            ull bx23 = *(const ull*)&Xt[c*64 + tn*4 + 2];
            #pragma unroll
            for (int i = 0; i < 4; i++){
                ull a2 = Wt2[(to*4 + i)*65 + c];
                acc2[i][0] = ffma2(a2, bx01, acc2[i][0]);
                acc2[i][1] = ffma2(a2, bx23, acc2[i][1]);
            }
        }
    }
    #pragma unroll
    for (int i = 0; i < 4; i++){
        int o = o0 + to*4 + i;
        float s  = pg[o] * rsqrtf(pvv[o] + EPSBN);
        float mu = pm[o], be = pb[o];
        float2 a = f2unpack(acc2[i][0]);
        float2 c = f2unpack(acc2[i][1]);
        float4 v4;
        v4.x = fmaxf((a.x-mu)*s + be, 0.f);
        v4.y = fmaxf((a.y-mu)*s + be, 0.f);
        v4.z = fmaxf((c.x-mu)*s + be, 0.f);
        v4.w = fmaxf((c.y-mu)*s + be, 0.f);
        *(float4*)&out[((size_t)b*DIMC + o)*NPIX + n0 + tn*4] = v4;
    }
}

// ================= launch ====================================================
extern "C" void kernel_launch(void* const* d_in, const int* in_sizes, int n_in,
                              void* d_out, int out_size)
{
    const float* x      = (const float*)d_in[0];
    const float* dw_w   = (const float*)d_in[1];
    const float* dw_g   = (const float*)d_in[2];
    const float* dw_b   = (const float*)d_in[3];
    const float* dw_m   = (const float*)d_in[4];
    const float* dw_v   = (const float*)d_in[5];
    const float* q_w    = (const float*)d_in[6];
    const float* q_g    = (const float*)d_in[7];
    const float* q_b    = (const float*)d_in[8];
    const float* q_m    = (const float*)d_in[9];
    const float* q_v    = (const float*)d_in[10];
    const float* k_w    = (const float*)d_in[11];
    const float* k_g    = (const float*)d_in[12];
    const float* k_b    = (const float*)d_in[13];
    const float* k_m    = (const float*)d_in[14];
    const float* k_v    = (const float*)d_in[15];
    const float* v_w    = (const float*)d_in[16];
    const float* v_g    = (const float*)d_in[17];
    const float* v_b    = (const float*)d_in[18];
    const float* v_m    = (const float*)d_in[19];
    const float* v_v    = (const float*)d_in[20];
    const float* proj_w = (const float*)d_in[21];
    const float* proj_g = (const float*)d_in[22];
    const float* proj_b = (const float*)d_in[23];
    const float* proj_m = (const float*)d_in[24];
    const float* proj_v = (const float*)d_in[25];
    const float* attn_b = (const float*)d_in[26];

    cudaFuncSetAttribute(qkv_kernel,
        cudaFuncAttributeMaxDynamicSharedMemorySize, QKV_SMEM);
    cudaFuncSetAttribute(attn_kernel,
        cudaFuncAttributeMaxDynamicSharedMemorySize, ATTN_SMEM);
    cudaFuncSetAttribute(proj_kernel,
        cudaFuncAttributeMaxDynamicSharedMemorySize, PROJ_SMEM);

    for (int head = 0; head < NHEADS; head++){
        dwconv_kernel<<<BATCH*HDC, 256>>>(
            x, dw_w, dw_g, dw_b, dw_m, dw_v, head);
        qkv_kernel<<<dim3(5, BATCH, 2), QKV_T, QKV_SMEM>>>(
            q_w, q_g, q_b, q_m, q_v,
            k_w, k_g, k_b, k_m, k_v,
            v_w, v_g, v_b, v_m, v_v, head);
        attn_kernel<<<dim3(50, BATCH), 256, ATTN_SMEM>>>(attn_b, head);
    }
    proj_kernel<<<dim3(25, 4, BATCH), 256, PROJ_SMEM>>>(
        proj_w, proj_g, proj_b, proj_m, proj_v, (float*)d_out);
}